// round 11
// baseline (speedup 1.0000x reference)
#include <cuda_runtime.h>
#include <math.h>
#include <stdint.h>

// Problem constants
#define BATCH 8
#define CCH   512
#define NTOK  1024

// Scratch buffers (device globals — no allocation allowed)
__device__ float g_hn[BATCH * CCH * NTOK];        // GroupNorm1 output
__device__ float g_qkv[BATCH * 3 * CCH * NTOK];   // qkv conv output
__device__ float g_attn[BATCH * CCH * NTOK];      // attention output
__device__ float g_proj[BATCH * CCH * NTOK];      // proj conv output

// ---------------------------------------------------------------------------
// GroupNorm over 32 groups of 16 channels x 1024 spatial. One block per (b,g).
// ---------------------------------------------------------------------------
template <bool ADD_RES>
__global__ __launch_bounds__(256)
void gn_kernel(const float* __restrict__ x,
               const float* __restrict__ scale,
               const float* __restrict__ bias,
               const float* __restrict__ resid,
               float* __restrict__ out) {
    __shared__ float s_sum[256];
    __shared__ float s_sq[256];
    int blk = blockIdx.x;           // b*32 + g
    int g = blk & 31;
    size_t base = (size_t)blk * 16 * 1024;
    int tid = threadIdx.x;

    float sum = 0.f, sq = 0.f;
    for (int i = tid; i < 16384; i += 256) {
        float v = x[base + i];
        sum += v;
        sq += v * v;
    }
    s_sum[tid] = sum;
    s_sq[tid] = sq;
    __syncthreads();
    for (int off = 128; off; off >>= 1) {
        if (tid < off) {
            s_sum[tid] += s_sum[tid + off];
            s_sq[tid] += s_sq[tid + off];
        }
        __syncthreads();
    }
    float mean = s_sum[0] * (1.0f / 16384.0f);
    float var = s_sq[0] * (1.0f / 16384.0f) - mean * mean;
    float rstd = rsqrtf(var + 1e-5f);

    for (int i = tid; i < 16384; i += 256) {
        int c = g * 16 + (i >> 10);
        float v = (x[base + i] - mean) * rstd * scale[c] + bias[c];
        out[base + i] = ADD_RES ? resid[base + i] + v : v;
    }
}

// ---------------------------------------------------------------------------
// tf32 / cp.async helpers
// ---------------------------------------------------------------------------
__device__ __forceinline__ float to_tf32(float x) {
    float y;
    asm("cvt.rna.tf32.f32 %0, %1;" : "=f"(y) : "f"(x));
    return y;
}
__device__ __forceinline__ uint32_t tf32_bits(float x) {
    return __float_as_uint(to_tf32(x));
}

__device__ __forceinline__ void mma_tf32(float* c, const uint32_t* a, const uint32_t* b) {
    asm volatile(
        "mma.sync.aligned.m16n8k8.row.col.f32.tf32.tf32.f32 "
        "{%0,%1,%2,%3}, {%4,%5,%6,%7}, {%8,%9}, {%0,%1,%2,%3};"
        : "+f"(c[0]), "+f"(c[1]), "+f"(c[2]), "+f"(c[3])
        : "r"(a[0]), "r"(a[1]), "r"(a[2]), "r"(a[3]), "r"(b[0]), "r"(b[1]));
}

__device__ __forceinline__ void cpa16(void* smem_dst, const void* gmem_src) {
    uint32_t d = (uint32_t)__cvta_generic_to_shared(smem_dst);
    asm volatile("cp.async.cg.shared.global [%0], [%1], 16;" :: "r"(d), "l"(gmem_src));
}
__device__ __forceinline__ void cpa_commit() {
    asm volatile("cp.async.commit_group;" ::: "memory");
}
__device__ __forceinline__ void cpa_wait0() {
    asm volatile("cp.async.wait_group 0;" ::: "memory");
}

// ---------------------------------------------------------------------------
// Batched tf32 tensor-core GEMM + bias, 2-stage cp.async pipeline:
//   C[z][m][n] = sum_k A[m][k] * B[z][k][n] + bias[m]
// Block tile 128x128, BK=32, 8 warps (4m x 2n), warp tile 32x64.
// Raw fp32 staged in smem (cp.async.cg 16B); tf32 rounding at fragment load.
// Dynamic smem: 2*(128*36 + 32*136)*4 = 71680 B.
// ---------------------------------------------------------------------------
__global__ __launch_bounds__(256)
void gemm_tf32_kernel(const float* __restrict__ A,
                      const float* __restrict__ Bm,
                      const float* __restrict__ bias,
                      float* __restrict__ Cm,
                      int M, int N, int K) {
    extern __shared__ float smp[];
    float* AsBuf[2] = {smp, smp + 4608};                 // [m][36]
    float* BsBuf[2] = {smp + 9216, smp + 13568};         // [k][136]

    const float* B = Bm + (size_t)blockIdx.z * K * N;
    float* Cp = Cm + (size_t)blockIdx.z * M * N;
    int m0 = blockIdx.y * 128;
    int n0 = blockIdx.x * 128;
    int tid = threadIdx.x;
    int lane = tid & 31;
    int warp = tid >> 5;
    int mw = (warp >> 1) * 32;
    int nw = (warp & 1) * 64;
    int lq = lane >> 2;
    int lr = lane & 3;

    float acc[2][8][4] = {};

    // Slab prefetch: A 128x32, B 32x128, both as 16B cp.async
    auto prefetch = [&](int k0, int stage) {
        float* as = AsBuf[stage];
        float* bs = BsBuf[stage];
#pragma unroll
        for (int it = 0; it < 4; it++) {
            int i = tid + it * 256;
            int m = i >> 3, k4 = (i & 7) * 4;
            cpa16(&as[m * 36 + k4], &A[(size_t)(m0 + m) * K + k0 + k4]);
        }
#pragma unroll
        for (int it = 0; it < 4; it++) {
            int i = tid + it * 256;
            int k = i >> 5, n4 = (i & 31) * 4;
            cpa16(&bs[k * 136 + n4], &B[(size_t)(k0 + k) * N + n0 + n4]);
        }
        cpa_commit();
    };

    int nslab = K >> 5;
    prefetch(0, 0);

    for (int s = 0; s < nslab; s++) {
        cpa_wait0();          // slab s resident (only pending group)
        __syncthreads();
        if (s + 1 < nslab) prefetch((s + 1) << 5, (s + 1) & 1);

        const float* as = AsBuf[s & 1];
        const float* bs = BsBuf[s & 1];
#pragma unroll
        for (int ks = 0; ks < 4; ks++) {
            int k8 = ks * 8;
            uint32_t a[2][4], b[8][2];
#pragma unroll
            for (int mi = 0; mi < 2; mi++) {
                int r = mw + 16 * mi + lq;
                a[mi][0] = tf32_bits(as[r * 36 + k8 + lr]);
                a[mi][1] = tf32_bits(as[(r + 8) * 36 + k8 + lr]);
                a[mi][2] = tf32_bits(as[r * 36 + k8 + lr + 4]);
                a[mi][3] = tf32_bits(as[(r + 8) * 36 + k8 + lr + 4]);
            }
#pragma unroll
            for (int ni = 0; ni < 8; ni++) {
                int c = nw + 8 * ni + lq;
                b[ni][0] = tf32_bits(bs[(k8 + lr) * 136 + c]);
                b[ni][1] = tf32_bits(bs[(k8 + lr + 4) * 136 + c]);
            }
#pragma unroll
            for (int mi = 0; mi < 2; mi++)
#pragma unroll
                for (int ni = 0; ni < 8; ni++)
                    mma_tf32(acc[mi][ni], a[mi], b[ni]);
        }
        __syncthreads();      // compute done before next prefetch overwrites
    }

    // Epilogue: bias + store
#pragma unroll
    for (int mi = 0; mi < 2; mi++) {
        int row0 = m0 + mw + 16 * mi + lq;
        float bi0 = bias[row0];
        float bi1 = bias[row0 + 8];
#pragma unroll
        for (int ni = 0; ni < 8; ni++) {
            int col = n0 + nw + 8 * ni + 2 * lr;
            float* p0 = &Cp[(size_t)row0 * N + col];
            float* p1 = &Cp[(size_t)(row0 + 8) * N + col];
            p0[0] = acc[mi][ni][0] + bi0;
            p0[1] = acc[mi][ni][1] + bi0;
            p1[0] = acc[mi][ni][2] + bi1;
            p1[1] = acc[mi][ni][3] + bi1;
        }
    }
}

// ---------------------------------------------------------------------------
// Tensor-core flash attention (unchanged from R8 passing version).
// ---------------------------------------------------------------------------
__global__ __launch_bounds__(256)
void attn_tc_kernel(const float* __restrict__ qkv,
                    float* __restrict__ aout) {
    extern __shared__ float sm[];
    float(*qs)[68]  = (float(*)[68])sm;                         // [t=128][c=64]
    float(*ks)[72]  = (float(*)[72])(sm + 128 * 68);            // [c=64][s=64]
    float(*vsT)[72] = (float(*)[72])(sm + 128 * 68 + 64 * 72);  // [s=64][c=64]
    float(*Ps)[68]  = (float(*)[68])(sm + 128 * 68 + 2 * 64 * 72); // [t=128][s=64]

    int bh = blockIdx.y;
    int t0 = blockIdx.x * 128;
    int b = bh >> 3, h = bh & 7;
    const float* base = qkv + ((size_t)b * 1536 + h * 192) * 1024;
    int tid = threadIdx.x;
    int lane = tid & 31;
    int warp = tid >> 5;
    int lq = lane >> 2;
    int lr = lane & 3;
    int rw = warp * 16;
    int r0 = rw + lq, r1 = rw + lq + 8;

#pragma unroll
    for (int it = 0; it < 32; it++) {
        int i = tid + it * 256;
        int c = i >> 7, t = i & 127;
        qs[t][c] = to_tf32(base[c * 1024 + t0 + t] * 0.125f);
    }

    float m0v = -INFINITY, m1v = -INFINITY, l0 = 0.f, l1 = 0.f;
    float accO[8][4] = {};
    __syncthreads();

    for (int s0 = 0; s0 < 1024; s0 += 64) {
#pragma unroll
        for (int it = 0; it < 4; it++) {
            int i = tid + it * 256;
            int c = i >> 4, s4 = (i & 15) * 4;
            float4 v = *(const float4*)&base[(64 + c) * 1024 + s0 + s4];
            v.x = to_tf32(v.x); v.y = to_tf32(v.y);
            v.z = to_tf32(v.z); v.w = to_tf32(v.w);
            *(float4*)&ks[c][s4] = v;
        }
#pragma unroll
        for (int it = 0; it < 16; it++) {
            int i = tid + it * 256;
            int c = i >> 6, s = i & 63;
            vsT[s][c] = to_tf32(base[(128 + c) * 1024 + s0 + s]);
        }
        __syncthreads();

        float accS[8][4] = {};
#pragma unroll
        for (int ks8 = 0; ks8 < 8; ks8++) {
            int k8 = ks8 * 8;
            uint32_t a[4];
            a[0] = __float_as_uint(qs[r0][k8 + lr]);
            a[1] = __float_as_uint(qs[r1][k8 + lr]);
            a[2] = __float_as_uint(qs[r0][k8 + lr + 4]);
            a[3] = __float_as_uint(qs[r1][k8 + lr + 4]);
#pragma unroll
            for (int ni = 0; ni < 8; ni++) {
                uint32_t bb[2];
                bb[0] = __float_as_uint(ks[k8 + lr][8 * ni + lq]);
                bb[1] = __float_as_uint(ks[k8 + lr + 4][8 * ni + lq]);
                mma_tf32(accS[ni], a, bb);
            }
        }

        float rm0 = -INFINITY, rm1 = -INFINITY;
#pragma unroll
        for (int ni = 0; ni < 8; ni++) {
            rm0 = fmaxf(rm0, fmaxf(accS[ni][0], accS[ni][1]));
            rm1 = fmaxf(rm1, fmaxf(accS[ni][2], accS[ni][3]));
        }
        rm0 = fmaxf(rm0, __shfl_xor_sync(0xffffffffu, rm0, 1));
        rm0 = fmaxf(rm0, __shfl_xor_sync(0xffffffffu, rm0, 2));
        rm1 = fmaxf(rm1, __shfl_xor_sync(0xffffffffu, rm1, 1));
        rm1 = fmaxf(rm1, __shfl_xor_sync(0xffffffffu, rm1, 2));
        float mn0 = fmaxf(m0v, rm0), mn1 = fmaxf(m1v, rm1);
        float corr0 = __expf(m0v - mn0), corr1 = __expf(m1v - mn1);
        float ps0 = 0.f, ps1 = 0.f;
#pragma unroll
        for (int ni = 0; ni < 8; ni++) {
            float p00 = __expf(accS[ni][0] - mn0);
            float p01 = __expf(accS[ni][1] - mn0);
            float p10 = __expf(accS[ni][2] - mn1);
            float p11 = __expf(accS[ni][3] - mn1);
            ps0 += p00 + p01;
            ps1 += p10 + p11;
            int c = 8 * ni + 2 * lr;
            Ps[r0][c]     = to_tf32(p00);
            Ps[r0][c + 1] = to_tf32(p01);
            Ps[r1][c]     = to_tf32(p10);
            Ps[r1][c + 1] = to_tf32(p11);
        }
        ps0 += __shfl_xor_sync(0xffffffffu, ps0, 1);
        ps0 += __shfl_xor_sync(0xffffffffu, ps0, 2);
        ps1 += __shfl_xor_sync(0xffffffffu, ps1, 1);
        ps1 += __shfl_xor_sync(0xffffffffu, ps1, 2);
        l0 = l0 * corr0 + ps0;
        l1 = l1 * corr1 + ps1;
        m0v = mn0; m1v = mn1;
#pragma unroll
        for (int ni = 0; ni < 8; ni++) {
            accO[ni][0] *= corr0; accO[ni][1] *= corr0;
            accO[ni][2] *= corr1; accO[ni][3] *= corr1;
        }
        __syncwarp();

#pragma unroll
        for (int ks8 = 0; ks8 < 8; ks8++) {
            int k8 = ks8 * 8;
            uint32_t a[4];
            a[0] = __float_as_uint(Ps[r0][k8 + lr]);
            a[1] = __float_as_uint(Ps[r1][k8 + lr]);
            a[2] = __float_as_uint(Ps[r0][k8 + lr + 4]);
            a[3] = __float_as_uint(Ps[r1][k8 + lr + 4]);
#pragma unroll
            for (int ni = 0; ni < 8; ni++) {
                uint32_t bb[2];
                bb[0] = __float_as_uint(vsT[k8 + lr][8 * ni + lq]);
                bb[1] = __float_as_uint(vsT[k8 + lr + 4][8 * ni + lq]);
                mma_tf32(accO[ni], a, bb);
            }
        }
        __syncthreads();
    }

    float inv0 = 1.0f / l0, inv1 = 1.0f / l1;
    float(*outS)[132] = (float(*)[132])sm;
#pragma unroll
    for (int ni = 0; ni < 8; ni++) {
        int c = 8 * ni + 2 * lr;
        outS[c][r0]     = accO[ni][0] * inv0;
        outS[c + 1][r0] = accO[ni][1] * inv0;
        outS[c][r1]     = accO[ni][2] * inv1;
        outS[c + 1][r1] = accO[ni][3] * inv1;
    }
    __syncthreads();

    size_t obase = ((size_t)b * 512 + h * 64) * 1024 + t0;
#pragma unroll
    for (int it = 0; it < 8; it++) {
        int i = tid + it * 256;
        int c = i >> 5, t4 = (i & 31) * 4;
        *(float4*)&aout[obase + (size_t)c * 1024 + t4] = *(const float4*)&outS[c][t4];
    }
}

// ---------------------------------------------------------------------------
// Launch
// ---------------------------------------------------------------------------
extern "C" void kernel_launch(void* const* d_in, const int* in_sizes, int n_in,
                              void* d_out, int out_size) {
    const float* x      = (const float*)d_in[0];
    const float* gn1_s  = (const float*)d_in[1];
    const float* gn1_b  = (const float*)d_in[2];
    const float* w_qkv  = (const float*)d_in[3];
    const float* b_qkv  = (const float*)d_in[4];
    const float* w_proj = (const float*)d_in[5];
    const float* b_proj = (const float*)d_in[6];
    const float* gn2_s  = (const float*)d_in[7];
    const float* gn2_b  = (const float*)d_in[8];
    float* out = (float*)d_out;

    float *hn, *qkv, *attn, *proj;
    cudaGetSymbolAddress((void**)&hn, g_hn);
    cudaGetSymbolAddress((void**)&qkv, g_qkv);
    cudaGetSymbolAddress((void**)&attn, g_attn);
    cudaGetSymbolAddress((void**)&proj, g_proj);

    const int GEMM_SMEM = 2 * (128 * 36 + 32 * 136) * 4;            // 71680 B
    const int ATTN_SMEM = (128 * 68 + 2 * 64 * 72 + 128 * 68) * 4;  // 106496 B
    cudaFuncSetAttribute(gemm_tf32_kernel, cudaFuncAttributeMaxDynamicSharedMemorySize,
                         GEMM_SMEM);
    cudaFuncSetAttribute(attn_tc_kernel, cudaFuncAttributeMaxDynamicSharedMemorySize,
                         ATTN_SMEM);

    // 1) GroupNorm1
    gn_kernel<false><<<256, 256>>>(x, gn1_s, gn1_b, nullptr, hn);
    // 2) qkv = W_qkv @ hn + b  (batched: 1536 x 1024 x 512, 8 batches)
    gemm_tf32_kernel<<<dim3(8, 12, 8), 256, GEMM_SMEM>>>(w_qkv, hn, b_qkv, qkv, 1536, 1024, 512);
    // 3) tensor-core flash attention per (bh, 128-row t-tile)
    attn_tc_kernel<<<dim3(8, 64), 256, ATTN_SMEM>>>(qkv, attn);
    // 4) proj = W_proj @ a + b  (512 x 1024 x 512, 8 batches)
    gemm_tf32_kernel<<<dim3(8, 4, 8), 256, GEMM_SMEM>>>(w_proj, attn, b_proj, proj, 512, 1024, 512);
    // 5) GroupNorm2 + residual
    gn_kernel<true><<<256, 256>>>(proj, gn2_s, gn2_b, x, out);
}

// round 12
// speedup vs baseline: 1.2203x; 1.2203x over previous
#include <cuda_runtime.h>
#include <math.h>
#include <stdint.h>

// Problem constants
#define BATCH 8
#define CCH   512
#define NTOK  1024

// Scratch buffers (device globals — no allocation allowed)
__device__ float g_hn[BATCH * CCH * NTOK];        // GroupNorm1 output
__device__ float g_qkv[BATCH * 3 * CCH * NTOK];   // qkv conv output
__device__ float g_attn[BATCH * CCH * NTOK];      // attention output
__device__ float g_proj[BATCH * CCH * NTOK];      // proj conv output

// ---------------------------------------------------------------------------
// GroupNorm, vectorized: 1024 threads/block, one block per (b,g).
// 16384 floats = 4096 float4 per block; channel == 256 consecutive float4.
// ---------------------------------------------------------------------------
template <bool ADD_RES>
__global__ __launch_bounds__(1024)
void gn_kernel(const float4* __restrict__ x,
               const float* __restrict__ scale,
               const float* __restrict__ bias,
               const float4* __restrict__ resid,
               float4* __restrict__ out) {
    __shared__ float s_sum[32];
    __shared__ float s_sq[32];
    int blk = blockIdx.x;           // b*32 + g
    int g = blk & 31;
    size_t base = (size_t)blk * 4096;   // float4 units
    int tid = threadIdx.x;
    int lane = tid & 31, warp = tid >> 5;

    float sum = 0.f, sq = 0.f;
    float4 v[4];
#pragma unroll
    for (int it = 0; it < 4; it++) {
        v[it] = x[base + tid + it * 1024];
        sum += v[it].x + v[it].y + v[it].z + v[it].w;
        sq += v[it].x * v[it].x + v[it].y * v[it].y
            + v[it].z * v[it].z + v[it].w * v[it].w;
    }
#pragma unroll
    for (int o = 16; o; o >>= 1) {
        sum += __shfl_xor_sync(0xffffffffu, sum, o);
        sq  += __shfl_xor_sync(0xffffffffu, sq, o);
    }
    if (lane == 0) { s_sum[warp] = sum; s_sq[warp] = sq; }
    __syncthreads();
    if (warp == 0) {
        float a = s_sum[lane], b2 = s_sq[lane];
#pragma unroll
        for (int o = 16; o; o >>= 1) {
            a  += __shfl_xor_sync(0xffffffffu, a, o);
            b2 += __shfl_xor_sync(0xffffffffu, b2, o);
        }
        if (lane == 0) { s_sum[0] = a; s_sq[0] = b2; }
    }
    __syncthreads();
    float mean = s_sum[0] * (1.0f / 16384.0f);
    float var = s_sq[0] * (1.0f / 16384.0f) - mean * mean;
    float rstd = rsqrtf(var + 1e-5f);

#pragma unroll
    for (int it = 0; it < 4; it++) {
        int j = tid + it * 1024;            // float4 index within block slab
        int c = g * 16 + (j >> 8);          // channel (256 float4 per channel)
        float a = rstd * scale[c];
        float bb = bias[c] - mean * a;
        float4 o;
        o.x = v[it].x * a + bb;
        o.y = v[it].y * a + bb;
        o.z = v[it].z * a + bb;
        o.w = v[it].w * a + bb;
        if (ADD_RES) {
            float4 r = resid[base + j];
            o.x += r.x; o.y += r.y; o.z += r.z; o.w += r.w;
        }
        out[base + j] = o;
    }
}

// ---------------------------------------------------------------------------
// tf32 helpers
// ---------------------------------------------------------------------------
__device__ __forceinline__ float to_tf32(float x) {
    float y;
    asm("cvt.rna.tf32.f32 %0, %1;" : "=f"(y) : "f"(x));
    return y;
}

__device__ __forceinline__ void mma_tf32(float* c, const uint32_t* a, const uint32_t* b) {
    asm volatile(
        "mma.sync.aligned.m16n8k8.row.col.f32.tf32.tf32.f32 "
        "{%0,%1,%2,%3}, {%4,%5,%6,%7}, {%8,%9}, {%0,%1,%2,%3};"
        : "+f"(c[0]), "+f"(c[1]), "+f"(c[2]), "+f"(c[3])
        : "r"(a[0]), "r"(a[1]), "r"(a[2]), "r"(a[3]), "r"(b[0]), "r"(b[1]));
}

// ---------------------------------------------------------------------------
// Batched tf32 tensor-core GEMM + bias (exact R8 version — 2 blocks/SM):
//   C[z][m][n] = sum_k A[m][k] * B[z][k][n] + bias[m]
// ---------------------------------------------------------------------------
__global__ __launch_bounds__(256)
void gemm_tf32_kernel(const float* __restrict__ A,
                      const float* __restrict__ Bm,
                      const float* __restrict__ bias,
                      float* __restrict__ Cm,
                      int M, int N, int K) {
    __shared__ float As[128][36];   // [m][k]
    __shared__ float Bs[32][136];   // [k][n]

    const float* B = Bm + (size_t)blockIdx.z * K * N;
    float* Cp = Cm + (size_t)blockIdx.z * M * N;
    int m0 = blockIdx.y * 128;
    int n0 = blockIdx.x * 128;
    int tid = threadIdx.x;
    int lane = tid & 31;
    int warp = tid >> 5;
    int mw = (warp >> 1) * 32;
    int nw = (warp & 1) * 64;
    int lq = lane >> 2;
    int lr = lane & 3;

    float acc[2][8][4] = {};

    for (int k0 = 0; k0 < K; k0 += 32) {
#pragma unroll
        for (int it = 0; it < 4; it++) {
            int i = tid + it * 256;
            int m = i >> 3, k4 = i & 7;
            float4 v = *(const float4*)&A[(size_t)(m0 + m) * K + k0 + k4 * 4];
            v.x = to_tf32(v.x); v.y = to_tf32(v.y);
            v.z = to_tf32(v.z); v.w = to_tf32(v.w);
            *(float4*)&As[m][k4 * 4] = v;
        }
#pragma unroll
        for (int it = 0; it < 4; it++) {
            int i = tid + it * 256;
            int k = i >> 5, n4 = i & 31;
            float4 v = *(const float4*)&B[(size_t)(k0 + k) * N + n0 + n4 * 4];
            v.x = to_tf32(v.x); v.y = to_tf32(v.y);
            v.z = to_tf32(v.z); v.w = to_tf32(v.w);
            *(float4*)&Bs[k][n4 * 4] = v;
        }
        __syncthreads();

#pragma unroll
        for (int ks = 0; ks < 4; ks++) {
            int k8 = ks * 8;
            uint32_t a[2][4], b[8][2];
#pragma unroll
            for (int mi = 0; mi < 2; mi++) {
                int r = mw + 16 * mi + lq;
                a[mi][0] = __float_as_uint(As[r][k8 + lr]);
                a[mi][1] = __float_as_uint(As[r + 8][k8 + lr]);
                a[mi][2] = __float_as_uint(As[r][k8 + lr + 4]);
                a[mi][3] = __float_as_uint(As[r + 8][k8 + lr + 4]);
            }
#pragma unroll
            for (int ni = 0; ni < 8; ni++) {
                int c = nw + 8 * ni + lq;
                b[ni][0] = __float_as_uint(Bs[k8 + lr][c]);
                b[ni][1] = __float_as_uint(Bs[k8 + lr + 4][c]);
            }
#pragma unroll
            for (int mi = 0; mi < 2; mi++)
#pragma unroll
                for (int ni = 0; ni < 8; ni++)
                    mma_tf32(acc[mi][ni], a[mi], b[ni]);
        }
        __syncthreads();
    }

#pragma unroll
    for (int mi = 0; mi < 2; mi++) {
        int row0 = m0 + mw + 16 * mi + lq;
        float bi0 = bias[row0];
        float bi1 = bias[row0 + 8];
#pragma unroll
        for (int ni = 0; ni < 8; ni++) {
            int col = n0 + nw + 8 * ni + 2 * lr;
            float* p0 = &Cp[(size_t)row0 * N + col];
            float* p1 = &Cp[(size_t)(row0 + 8) * N + col];
            p0[0] = acc[mi][ni][0] + bi0;
            p0[1] = acc[mi][ni][1] + bi0;
            p1[0] = acc[mi][ni][2] + bi1;
            p1[1] = acc[mi][ni][3] + bi1;
        }
    }
}

// ---------------------------------------------------------------------------
// Tensor-core flash attention (unchanged from R8 passing version).
// ---------------------------------------------------------------------------
__global__ __launch_bounds__(256)
void attn_tc_kernel(const float* __restrict__ qkv,
                    float* __restrict__ aout) {
    extern __shared__ float sm[];
    float(*qs)[68]  = (float(*)[68])sm;                         // [t=128][c=64]
    float(*ks)[72]  = (float(*)[72])(sm + 128 * 68);            // [c=64][s=64]
    float(*vsT)[72] = (float(*)[72])(sm + 128 * 68 + 64 * 72);  // [s=64][c=64]
    float(*Ps)[68]  = (float(*)[68])(sm + 128 * 68 + 2 * 64 * 72); // [t=128][s=64]

    int bh = blockIdx.y;
    int t0 = blockIdx.x * 128;
    int b = bh >> 3, h = bh & 7;
    const float* base = qkv + ((size_t)b * 1536 + h * 192) * 1024;
    int tid = threadIdx.x;
    int lane = tid & 31;
    int warp = tid >> 5;
    int lq = lane >> 2;
    int lr = lane & 3;
    int rw = warp * 16;
    int r0 = rw + lq, r1 = rw + lq + 8;

#pragma unroll
    for (int it = 0; it < 32; it++) {
        int i = tid + it * 256;
        int c = i >> 7, t = i & 127;
        qs[t][c] = to_tf32(base[c * 1024 + t0 + t] * 0.125f);
    }

    float m0v = -INFINITY, m1v = -INFINITY, l0 = 0.f, l1 = 0.f;
    float accO[8][4] = {};
    __syncthreads();

    for (int s0 = 0; s0 < 1024; s0 += 64) {
#pragma unroll
        for (int it = 0; it < 4; it++) {
            int i = tid + it * 256;
            int c = i >> 4, s4 = (i & 15) * 4;
            float4 v = *(const float4*)&base[(64 + c) * 1024 + s0 + s4];
            v.x = to_tf32(v.x); v.y = to_tf32(v.y);
            v.z = to_tf32(v.z); v.w = to_tf32(v.w);
            *(float4*)&ks[c][s4] = v;
        }
#pragma unroll
        for (int it = 0; it < 16; it++) {
            int i = tid + it * 256;
            int c = i >> 6, s = i & 63;
            vsT[s][c] = to_tf32(base[(128 + c) * 1024 + s0 + s]);
        }
        __syncthreads();

        float accS[8][4] = {};
#pragma unroll
        for (int ks8 = 0; ks8 < 8; ks8++) {
            int k8 = ks8 * 8;
            uint32_t a[4];
            a[0] = __float_as_uint(qs[r0][k8 + lr]);
            a[1] = __float_as_uint(qs[r1][k8 + lr]);
            a[2] = __float_as_uint(qs[r0][k8 + lr + 4]);
            a[3] = __float_as_uint(qs[r1][k8 + lr + 4]);
#pragma unroll
            for (int ni = 0; ni < 8; ni++) {
                uint32_t bb[2];
                bb[0] = __float_as_uint(ks[k8 + lr][8 * ni + lq]);
                bb[1] = __float_as_uint(ks[k8 + lr + 4][8 * ni + lq]);
                mma_tf32(accS[ni], a, bb);
            }
        }

        float rm0 = -INFINITY, rm1 = -INFINITY;
#pragma unroll
        for (int ni = 0; ni < 8; ni++) {
            rm0 = fmaxf(rm0, fmaxf(accS[ni][0], accS[ni][1]));
            rm1 = fmaxf(rm1, fmaxf(accS[ni][2], accS[ni][3]));
        }
        rm0 = fmaxf(rm0, __shfl_xor_sync(0xffffffffu, rm0, 1));
        rm0 = fmaxf(rm0, __shfl_xor_sync(0xffffffffu, rm0, 2));
        rm1 = fmaxf(rm1, __shfl_xor_sync(0xffffffffu, rm1, 1));
        rm1 = fmaxf(rm1, __shfl_xor_sync(0xffffffffu, rm1, 2));
        float mn0 = fmaxf(m0v, rm0), mn1 = fmaxf(m1v, rm1);
        float corr0 = __expf(m0v - mn0), corr1 = __expf(m1v - mn1);
        float ps0 = 0.f, ps1 = 0.f;
#pragma unroll
        for (int ni = 0; ni < 8; ni++) {
            float p00 = __expf(accS[ni][0] - mn0);
            float p01 = __expf(accS[ni][1] - mn0);
            float p10 = __expf(accS[ni][2] - mn1);
            float p11 = __expf(accS[ni][3] - mn1);
            ps0 += p00 + p01;
            ps1 += p10 + p11;
            int c = 8 * ni + 2 * lr;
            Ps[r0][c]     = to_tf32(p00);
            Ps[r0][c + 1] = to_tf32(p01);
            Ps[r1][c]     = to_tf32(p10);
            Ps[r1][c + 1] = to_tf32(p11);
        }
        ps0 += __shfl_xor_sync(0xffffffffu, ps0, 1);
        ps0 += __shfl_xor_sync(0xffffffffu, ps0, 2);
        ps1 += __shfl_xor_sync(0xffffffffu, ps1, 1);
        ps1 += __shfl_xor_sync(0xffffffffu, ps1, 2);
        l0 = l0 * corr0 + ps0;
        l1 = l1 * corr1 + ps1;
        m0v = mn0; m1v = mn1;
#pragma unroll
        for (int ni = 0; ni < 8; ni++) {
            accO[ni][0] *= corr0; accO[ni][1] *= corr0;
            accO[ni][2] *= corr1; accO[ni][3] *= corr1;
        }
        __syncwarp();

#pragma unroll
        for (int ks8 = 0; ks8 < 8; ks8++) {
            int k8 = ks8 * 8;
            uint32_t a[4];
            a[0] = __float_as_uint(Ps[r0][k8 + lr]);
            a[1] = __float_as_uint(Ps[r1][k8 + lr]);
            a[2] = __float_as_uint(Ps[r0][k8 + lr + 4]);
            a[3] = __float_as_uint(Ps[r1][k8 + lr + 4]);
#pragma unroll
            for (int ni = 0; ni < 8; ni++) {
                uint32_t bb[2];
                bb[0] = __float_as_uint(vsT[k8 + lr][8 * ni + lq]);
                bb[1] = __float_as_uint(vsT[k8 + lr + 4][8 * ni + lq]);
                mma_tf32(accO[ni], a, bb);
            }
        }
        __syncthreads();
    }

    float inv0 = 1.0f / l0, inv1 = 1.0f / l1;
    float(*outS)[132] = (float(*)[132])sm;
#pragma unroll
    for (int ni = 0; ni < 8; ni++) {
        int c = 8 * ni + 2 * lr;
        outS[c][r0]     = accO[ni][0] * inv0;
        outS[c + 1][r0] = accO[ni][1] * inv0;
        outS[c][r1]     = accO[ni][2] * inv1;
        outS[c + 1][r1] = accO[ni][3] * inv1;
    }
    __syncthreads();

    size_t obase = ((size_t)b * 512 + h * 64) * 1024 + t0;
#pragma unroll
    for (int it = 0; it < 8; it++) {
        int i = tid + it * 256;
        int c = i >> 5, t4 = (i & 31) * 4;
        *(float4*)&aout[obase + (size_t)c * 1024 + t4] = *(const float4*)&outS[c][t4];
    }
}

// ---------------------------------------------------------------------------
// Launch
// ---------------------------------------------------------------------------
extern "C" void kernel_launch(void* const* d_in, const int* in_sizes, int n_in,
                              void* d_out, int out_size) {
    const float* x      = (const float*)d_in[0];
    const float* gn1_s  = (const float*)d_in[1];
    const float* gn1_b  = (const float*)d_in[2];
    const float* w_qkv  = (const float*)d_in[3];
    const float* b_qkv  = (const float*)d_in[4];
    const float* w_proj = (const float*)d_in[5];
    const float* b_proj = (const float*)d_in[6];
    const float* gn2_s  = (const float*)d_in[7];
    const float* gn2_b  = (const float*)d_in[8];
    float* out = (float*)d_out;

    float *hn, *qkv, *attn, *proj;
    cudaGetSymbolAddress((void**)&hn, g_hn);
    cudaGetSymbolAddress((void**)&qkv, g_qkv);
    cudaGetSymbolAddress((void**)&attn, g_attn);
    cudaGetSymbolAddress((void**)&proj, g_proj);

    const int ATTN_SMEM = (128 * 68 + 2 * 64 * 72 + 128 * 68) * 4;  // 106496 B
    cudaFuncSetAttribute(attn_tc_kernel, cudaFuncAttributeMaxDynamicSharedMemorySize,
                         ATTN_SMEM);

    // 1) GroupNorm1 (vectorized)
    gn_kernel<false><<<256, 1024>>>((const float4*)x, gn1_s, gn1_b, nullptr,
                                    (float4*)hn);
    // 2) qkv = W_qkv @ hn + b  (batched: 1536 x 1024 x 512, 8 batches)
    gemm_tf32_kernel<<<dim3(8, 12, 8), 256>>>(w_qkv, hn, b_qkv, qkv, 1536, 1024, 512);
    // 3) tensor-core flash attention per (bh, 128-row t-tile)
    attn_tc_kernel<<<dim3(8, 64), 256, ATTN_SMEM>>>(qkv, attn);
    // 4) proj = W_proj @ a + b  (512 x 1024 x 512, 8 batches)
    gemm_tf32_kernel<<<dim3(8, 4, 8), 256>>>(w_proj, attn, b_proj, proj, 512, 1024, 512);
    // 5) GroupNorm2 + residual (vectorized)
    gn_kernel<true><<<256, 1024>>>((const float4*)proj, gn2_s, gn2_b,
                                   (const float4*)x, (float4*)out);
}